// round 13
// baseline (speedup 1.0000x reference)
#include <cuda_runtime.h>

// out[r][c] = posenc(X[r]) . W[3*voxel_ids[p] + c],  r = row_ids[p]
//
//  K1 rank:    pos[p] = atomicAdd(cnt[v],1)          (plain 1pt — fastest measured, R9)
//  K2 scan:    exclusive scan -> g_binstart; counters self-reset
//  K3 scatter: g_pts[binstart[v]+pos[p]] = float4(x, bits(r))   (plain 1pt, R9)
//  K4 main:    2 CTAs per voxel, 1 pt/thread; smem weights packed float4 with
//              angle PAIRS (sin,cos,sin,cos) -> 48 LDS.128/pt (was 96 LDS.64);
//              frequency loop in pairs (f=2k,2k+1) with double-angle recurrence
//              (6 MUFU/pt). Reg cap (256,6).

#define NUM_VOXELS 512
#define NPTS_MAX (1 << 18)
#define PAD 32                    // counter stride in ints = 128 B

__device__ int    g_cnt[NUM_VOXELS * PAD];   // zero-init; self-reset by K2
__device__ int    g_pos[NPTS_MAX];
__device__ int    g_binstart[NUM_VOXELS + 1];
__device__ float4 g_pts[NPTS_MAX];

// ---- K1: per-point rank within its voxel ----
__global__ void __launch_bounds__(256)
rank_kernel(const int* __restrict__ voxel_ids, int n)
{
    int p = blockIdx.x * 256 + threadIdx.x;
    if (p >= n) return;
    g_pos[p] = atomicAdd(&g_cnt[voxel_ids[p] * PAD], 1);
}

// ---- K2: scan counts -> binstart; self-reset counters ----
__global__ void __launch_bounds__(NUM_VOXELS)
scan_kernel(int n)
{
    __shared__ int sh[NUM_VOXELS];
    const int t = threadIdx.x;
    const int val = g_cnt[t * PAD];
    g_cnt[t * PAD] = 0;                  // reset for next graph replay
    sh[t] = val;
    __syncthreads();
#pragma unroll
    for (int off = 1; off < NUM_VOXELS; off <<= 1) {
        int x = sh[t];
        if (t >= off) x += sh[t - off];
        __syncthreads();
        sh[t] = x;
        __syncthreads();
    }
    g_binstart[t] = sh[t] - val;         // exclusive
    if (t == NUM_VOXELS - 1) g_binstart[NUM_VOXELS] = n;
}

// ---- K3: scatter payload into voxel-sorted order ----
__global__ void __launch_bounds__(256)
scatter_kernel(const float* __restrict__ X,
               const int* __restrict__ row_ids,
               const int* __restrict__ voxel_ids,
               int n)
{
    int p = blockIdx.x * 256 + threadIdx.x;
    if (p >= n) return;
    const int v = voxel_ids[p];
    const int dst = g_binstart[v] + g_pos[p];
    const int r = row_ids[p];
    float4 pay;
    pay.x = X[3 * r + 0];
    pay.y = X[3 * r + 1];
    pay.z = X[3 * r + 2];
    pay.w = __int_as_float(r);
    g_pts[dst] = pay;
}

// ---- K4: main — 2 CTAs/voxel, float4-paired weights, double-angle ----
// Wq[c][q] (q<15): (sw[2q], cw[2q], sw[2q+1], cw[2q+1]) for angles a=3f+d
// Wq[c][15]: (raw0, raw1, raw2, 0)
__global__ void __launch_bounds__(256, 6)
voxel_main_kernel(const float* __restrict__ W,
                  float* __restrict__ out)
{
    __shared__ float4 Wq[3][16];
    const int v    = blockIdx.x >> 1;
    const int half = blockIdx.x & 1;
    const int t = threadIdx.x;

    if (t < 45) {
        const int c = t / 15, q = t - 15 * c;
        const float* row = W + (3 * v + c) * 63;
        const int a0 = 2 * q,     f0 = a0 / 3, d0 = a0 - 3 * f0;
        const int a1 = 2 * q + 1, f1 = a1 / 3, d1 = a1 - 3 * f1;
        Wq[c][q] = make_float4(row[3 + 6 * f0 + d0], row[3 + 6 * f0 + 3 + d0],
                               row[3 + 6 * f1 + d1], row[3 + 6 * f1 + 3 + d1]);
    } else if (t < 48) {
        const int c = t - 45;
        const float* row = W + (3 * v + c) * 63;
        Wq[c][15] = make_float4(row[0], row[1], row[2], 0.0f);
    }
    __syncthreads();

    const int start = g_binstart[v];
    const int cnt   = g_binstart[v + 1] - start;

    for (int i = half * 256 + t; i < cnt; i += 512) {
        const float4 pay = g_pts[start + i];
        const float x0 = pay.x, x1 = pay.y, x2 = pay.z;
        const int   r  = __float_as_int(pay.w);

        const float4 rw0 = Wq[0][15], rw1 = Wq[1][15], rw2 = Wq[2][15];
        float a0 = x0 * rw0.x; a0 = fmaf(x1, rw0.y, a0); a0 = fmaf(x2, rw0.z, a0);
        float a1 = x0 * rw1.x; a1 = fmaf(x1, rw1.y, a1); a1 = fmaf(x2, rw1.z, a1);
        float a2 = x0 * rw2.x; a2 = fmaf(x1, rw2.y, a2); a2 = fmaf(x2, rw2.z, a2);

        // base angles (f=0)
        float s0, c0, s1, c1, s2, c2;
        __sincosf(x0, &s0, &c0);
        __sincosf(x1, &s1, &c1);
        __sincosf(x2, &s2, &c2);

#pragma unroll
        for (int k = 0; k < 5; ++k) {
            // doubled angles for f = 2k+1
            float ts, S0, C0, S1, C1, S2, C2;
            ts = s0 * c0; S0 = ts + ts; C0 = fmaf(c0, c0, -(s0 * s0));
            ts = s1 * c1; S1 = ts + ts; C1 = fmaf(c1, c1, -(s1 * s1));
            ts = s2 * c2; S2 = ts + ts; C2 = fmaf(c2, c2, -(s2 * s2));

            {
                const float4 A = Wq[0][3 * k], B = Wq[0][3 * k + 1], Cq = Wq[0][3 * k + 2];
                a0 = fmaf(s0, A.x, a0); a0 = fmaf(c0, A.y, a0);
                a0 = fmaf(s1, A.z, a0); a0 = fmaf(c1, A.w, a0);
                a0 = fmaf(s2, B.x, a0); a0 = fmaf(c2, B.y, a0);
                a0 = fmaf(S0, B.z, a0); a0 = fmaf(C0, B.w, a0);
                a0 = fmaf(S1, Cq.x, a0); a0 = fmaf(C1, Cq.y, a0);
                a0 = fmaf(S2, Cq.z, a0); a0 = fmaf(C2, Cq.w, a0);
            }
            {
                const float4 A = Wq[1][3 * k], B = Wq[1][3 * k + 1], Cq = Wq[1][3 * k + 2];
                a1 = fmaf(s0, A.x, a1); a1 = fmaf(c0, A.y, a1);
                a1 = fmaf(s1, A.z, a1); a1 = fmaf(c1, A.w, a1);
                a1 = fmaf(s2, B.x, a1); a1 = fmaf(c2, B.y, a1);
                a1 = fmaf(S0, B.z, a1); a1 = fmaf(C0, B.w, a1);
                a1 = fmaf(S1, Cq.x, a1); a1 = fmaf(C1, Cq.y, a1);
                a1 = fmaf(S2, Cq.z, a1); a1 = fmaf(C2, Cq.w, a1);
            }
            {
                const float4 A = Wq[2][3 * k], B = Wq[2][3 * k + 1], Cq = Wq[2][3 * k + 2];
                a2 = fmaf(s0, A.x, a2); a2 = fmaf(c0, A.y, a2);
                a2 = fmaf(s1, A.z, a2); a2 = fmaf(c1, A.w, a2);
                a2 = fmaf(s2, B.x, a2); a2 = fmaf(c2, B.y, a2);
                a2 = fmaf(S0, B.z, a2); a2 = fmaf(C0, B.w, a2);
                a2 = fmaf(S1, Cq.x, a2); a2 = fmaf(C1, Cq.y, a2);
                a2 = fmaf(S2, Cq.z, a2); a2 = fmaf(C2, Cq.w, a2);
            }

            if (k < 4) {   // advance to f = 2k+2: double the doubled
                ts = S0 * C0; s0 = ts + ts; c0 = fmaf(C0, C0, -(S0 * S0));
                ts = S1 * C1; s1 = ts + ts; c1 = fmaf(C1, C1, -(S1 * S1));
                ts = S2 * C2; s2 = ts + ts; c2 = fmaf(C2, C2, -(S2 * S2));
            }
        }

        out[3 * r + 0] = a0;
        out[3 * r + 1] = a1;
        out[3 * r + 2] = a2;
    }
}

extern "C" void kernel_launch(void* const* d_in, const int* in_sizes, int n_in,
                              void* d_out, int out_size)
{
    const float* X         = (const float*)d_in[0];
    const float* W         = (const float*)d_in[1];
    const int*   row_ids   = (const int*)d_in[2];
    const int*   voxel_ids = (const int*)d_in[3];
    float*       out       = (float*)d_out;

    const int n = in_sizes[0] / 3;               // N_POINTS
    const int nb = (n + 255) / 256;

    rank_kernel<<<nb, 256>>>(voxel_ids, n);
    scan_kernel<<<1, NUM_VOXELS>>>(n);
    scatter_kernel<<<nb, 256>>>(X, row_ids, voxel_ids, n);
    voxel_main_kernel<<<NUM_VOXELS * 2, 256>>>(W, out);
}

// round 15
// speedup vs baseline: 1.1824x; 1.1824x over previous
#include <cuda_runtime.h>

// out[r][c] = posenc(X[r]) . W[3*voxel_ids[p] + c],  r = row_ids[p]
//
//  K1 rank:    pos[p] = atomicAdd(cnt[v],1)          (plain 1pt — fastest measured)
//  K2 scan:    exclusive scan -> g_binstart; counters self-reset
//  K3 scatter: g_pts[binstart[v]+pos[p]] = float4(x, bits(r))
//  K4 main:    2 CTAs per voxel, 1 pt/thread; smem weights as float4 angle
//              pairs (48 LDS.128/pt), frequency pairs + double-angle (6 MUFU/pt).
//              Reg cap (256,5)=51 regs — R13's (256,6)=40 caused local-memory
//              spills (DRAM 27.5%, 89 MB). 5 CTAs/SM still hides latency.

#define NUM_VOXELS 512
#define NPTS_MAX (1 << 18)
#define PAD 32                    // counter stride in ints = 128 B

__device__ int    g_cnt[NUM_VOXELS * PAD];   // zero-init; self-reset by K2
__device__ int    g_pos[NPTS_MAX];
__device__ int    g_binstart[NUM_VOXELS + 1];
__device__ float4 g_pts[NPTS_MAX];

// ---- K1: per-point rank within its voxel ----
__global__ void __launch_bounds__(256)
rank_kernel(const int* __restrict__ voxel_ids, int n)
{
    int p = blockIdx.x * 256 + threadIdx.x;
    if (p >= n) return;
    g_pos[p] = atomicAdd(&g_cnt[voxel_ids[p] * PAD], 1);
}

// ---- K2: scan counts -> binstart; self-reset counters ----
__global__ void __launch_bounds__(NUM_VOXELS)
scan_kernel(int n)
{
    __shared__ int sh[NUM_VOXELS];
    const int t = threadIdx.x;
    const int val = g_cnt[t * PAD];
    g_cnt[t * PAD] = 0;                  // reset for next graph replay
    sh[t] = val;
    __syncthreads();
#pragma unroll
    for (int off = 1; off < NUM_VOXELS; off <<= 1) {
        int x = sh[t];
        if (t >= off) x += sh[t - off];
        __syncthreads();
        sh[t] = x;
        __syncthreads();
    }
    g_binstart[t] = sh[t] - val;         // exclusive
    if (t == NUM_VOXELS - 1) g_binstart[NUM_VOXELS] = n;
}

// ---- K3: scatter payload into voxel-sorted order ----
__global__ void __launch_bounds__(256)
scatter_kernel(const float* __restrict__ X,
               const int* __restrict__ row_ids,
               const int* __restrict__ voxel_ids,
               int n)
{
    int p = blockIdx.x * 256 + threadIdx.x;
    if (p >= n) return;
    const int v = voxel_ids[p];
    const int dst = g_binstart[v] + g_pos[p];
    const int r = row_ids[p];
    float4 pay;
    pay.x = X[3 * r + 0];
    pay.y = X[3 * r + 1];
    pay.z = X[3 * r + 2];
    pay.w = __int_as_float(r);
    g_pts[dst] = pay;
}

// ---- K4: main — 2 CTAs/voxel, float4-paired weights, double-angle ----
// Wq[c][q] (q<15): (sw[2q], cw[2q], sw[2q+1], cw[2q+1]) for angles a=3f+d
// Wq[c][15]: (raw0, raw1, raw2, 0)
__global__ void __launch_bounds__(256, 5)
voxel_main_kernel(const float* __restrict__ W,
                  float* __restrict__ out)
{
    __shared__ float4 Wq[3][16];
    const int v    = blockIdx.x >> 1;
    const int half = blockIdx.x & 1;
    const int t = threadIdx.x;

    if (t < 45) {
        const int c = t / 15, q = t - 15 * c;
        const float* row = W + (3 * v + c) * 63;
        const int a0 = 2 * q,     f0 = a0 / 3, d0 = a0 - 3 * f0;
        const int a1 = 2 * q + 1, f1 = a1 / 3, d1 = a1 - 3 * f1;
        Wq[c][q] = make_float4(row[3 + 6 * f0 + d0], row[3 + 6 * f0 + 3 + d0],
                               row[3 + 6 * f1 + d1], row[3 + 6 * f1 + 3 + d1]);
    } else if (t < 48) {
        const int c = t - 45;
        const float* row = W + (3 * v + c) * 63;
        Wq[c][15] = make_float4(row[0], row[1], row[2], 0.0f);
    }
    __syncthreads();

    const int start = g_binstart[v];
    const int cnt   = g_binstart[v + 1] - start;

    for (int i = half * 256 + t; i < cnt; i += 512) {
        const float4 pay = g_pts[start + i];
        const float x0 = pay.x, x1 = pay.y, x2 = pay.z;
        const int   r  = __float_as_int(pay.w);

        const float4 rw0 = Wq[0][15], rw1 = Wq[1][15], rw2 = Wq[2][15];
        float a0 = x0 * rw0.x; a0 = fmaf(x1, rw0.y, a0); a0 = fmaf(x2, rw0.z, a0);
        float a1 = x0 * rw1.x; a1 = fmaf(x1, rw1.y, a1); a1 = fmaf(x2, rw1.z, a1);
        float a2 = x0 * rw2.x; a2 = fmaf(x1, rw2.y, a2); a2 = fmaf(x2, rw2.z, a2);

        // base angles (f=0)
        float s0, c0, s1, c1, s2, c2;
        __sincosf(x0, &s0, &c0);
        __sincosf(x1, &s1, &c1);
        __sincosf(x2, &s2, &c2);

#pragma unroll
        for (int k = 0; k < 5; ++k) {
            // doubled angles for f = 2k+1
            float ts, S0, C0, S1, C1, S2, C2;
            ts = s0 * c0; S0 = ts + ts; C0 = fmaf(c0, c0, -(s0 * s0));
            ts = s1 * c1; S1 = ts + ts; C1 = fmaf(c1, c1, -(s1 * s1));
            ts = s2 * c2; S2 = ts + ts; C2 = fmaf(c2, c2, -(s2 * s2));

            {
                const float4 A = Wq[0][3 * k], B = Wq[0][3 * k + 1], Cq = Wq[0][3 * k + 2];
                a0 = fmaf(s0, A.x, a0); a0 = fmaf(c0, A.y, a0);
                a0 = fmaf(s1, A.z, a0); a0 = fmaf(c1, A.w, a0);
                a0 = fmaf(s2, B.x, a0); a0 = fmaf(c2, B.y, a0);
                a0 = fmaf(S0, B.z, a0); a0 = fmaf(C0, B.w, a0);
                a0 = fmaf(S1, Cq.x, a0); a0 = fmaf(C1, Cq.y, a0);
                a0 = fmaf(S2, Cq.z, a0); a0 = fmaf(C2, Cq.w, a0);
            }
            {
                const float4 A = Wq[1][3 * k], B = Wq[1][3 * k + 1], Cq = Wq[1][3 * k + 2];
                a1 = fmaf(s0, A.x, a1); a1 = fmaf(c0, A.y, a1);
                a1 = fmaf(s1, A.z, a1); a1 = fmaf(c1, A.w, a1);
                a1 = fmaf(s2, B.x, a1); a1 = fmaf(c2, B.y, a1);
                a1 = fmaf(S0, B.z, a1); a1 = fmaf(C0, B.w, a1);
                a1 = fmaf(S1, Cq.x, a1); a1 = fmaf(C1, Cq.y, a1);
                a1 = fmaf(S2, Cq.z, a1); a1 = fmaf(C2, Cq.w, a1);
            }
            {
                const float4 A = Wq[2][3 * k], B = Wq[2][3 * k + 1], Cq = Wq[2][3 * k + 2];
                a2 = fmaf(s0, A.x, a2); a2 = fmaf(c0, A.y, a2);
                a2 = fmaf(s1, A.z, a2); a2 = fmaf(c1, A.w, a2);
                a2 = fmaf(s2, B.x, a2); a2 = fmaf(c2, B.y, a2);
                a2 = fmaf(S0, B.z, a2); a2 = fmaf(C0, B.w, a2);
                a2 = fmaf(S1, Cq.x, a2); a2 = fmaf(C1, Cq.y, a2);
                a2 = fmaf(S2, Cq.z, a2); a2 = fmaf(C2, Cq.w, a2);
            }

            if (k < 4) {   // advance to f = 2k+2: double the doubled
                ts = S0 * C0; s0 = ts + ts; c0 = fmaf(C0, C0, -(S0 * S0));
                ts = S1 * C1; s1 = ts + ts; c1 = fmaf(C1, C1, -(S1 * S1));
                ts = S2 * C2; s2 = ts + ts; c2 = fmaf(C2, C2, -(S2 * S2));
            }
        }

        out[3 * r + 0] = a0;
        out[3 * r + 1] = a1;
        out[3 * r + 2] = a2;
    }
}

extern "C" void kernel_launch(void* const* d_in, const int* in_sizes, int n_in,
                              void* d_out, int out_size)
{
    const float* X         = (const float*)d_in[0];
    const float* W         = (const float*)d_in[1];
    const int*   row_ids   = (const int*)d_in[2];
    const int*   voxel_ids = (const int*)d_in[3];
    float*       out       = (float*)d_out;

    const int n = in_sizes[0] / 3;               // N_POINTS
    const int nb = (n + 255) / 256;

    rank_kernel<<<nb, 256>>>(voxel_ids, n);
    scan_kernel<<<1, NUM_VOXELS>>>(n);
    scatter_kernel<<<nb, 256>>>(X, row_ids, voxel_ids, n);
    voxel_main_kernel<<<NUM_VOXELS * 2, 256>>>(W, out);
}

// round 16
// speedup vs baseline: 1.9463x; 1.6460x over previous
#include <cuda_runtime.h>

// out[r][c] = posenc(X[r]) . W[3*voxel_ids[p] + c],  r = row_ids[p]
//
//  K1 rank:    pos[p] = atomicAdd(cnt[v],1)          (measured-best setup, R9)
//  K2 scan:    exclusive scan -> g_binstart; counters self-reset
//  K3 scatter: g_pts[binstart[v]+pos[p]] = float4(x, bits(r))
//  K4 main:    float2 (sin,cos)-paired smem weights (R11 body, 39 regs, no
//              spills at cap 6), double-angle recurrence (6 MUFU/pt), and
//              THIS ROUND: grid = 888 = one full wave; grid-stride over the
//              1024 voxel-half chunks to kill R9's 1.15-wave tail.

#define NUM_VOXELS 512
#define NPTS_MAX (1 << 18)
#define PAD 32                    // counter stride in ints = 128 B
#define K4_BLOCKS 888             // 148 SMs * 6 CTAs/SM
#define NCHUNKS (NUM_VOXELS * 2)  // 2 half-bins per voxel

__device__ int    g_cnt[NUM_VOXELS * PAD];   // zero-init; self-reset by K2
__device__ int    g_pos[NPTS_MAX];
__device__ int    g_binstart[NUM_VOXELS + 1];
__device__ float4 g_pts[NPTS_MAX];

// ---- K1: per-point rank within its voxel ----
__global__ void __launch_bounds__(256)
rank_kernel(const int* __restrict__ voxel_ids, int n)
{
    int p = blockIdx.x * 256 + threadIdx.x;
    if (p >= n) return;
    g_pos[p] = atomicAdd(&g_cnt[voxel_ids[p] * PAD], 1);
}

// ---- K2: scan counts -> binstart; self-reset counters ----
__global__ void __launch_bounds__(NUM_VOXELS)
scan_kernel(int n)
{
    __shared__ int sh[NUM_VOXELS];
    const int t = threadIdx.x;
    const int val = g_cnt[t * PAD];
    g_cnt[t * PAD] = 0;                  // reset for next graph replay
    sh[t] = val;
    __syncthreads();
#pragma unroll
    for (int off = 1; off < NUM_VOXELS; off <<= 1) {
        int x = sh[t];
        if (t >= off) x += sh[t - off];
        __syncthreads();
        sh[t] = x;
        __syncthreads();
    }
    g_binstart[t] = sh[t] - val;         // exclusive
    if (t == NUM_VOXELS - 1) g_binstart[NUM_VOXELS] = n;
}

// ---- K3: scatter payload into voxel-sorted order ----
__global__ void __launch_bounds__(256)
scatter_kernel(const float* __restrict__ X,
               const int* __restrict__ row_ids,
               const int* __restrict__ voxel_ids,
               int n)
{
    int p = blockIdx.x * 256 + threadIdx.x;
    if (p >= n) return;
    const int v = voxel_ids[p];
    const int dst = g_binstart[v] + g_pos[p];
    const int r = row_ids[p];
    float4 pay;
    pay.x = X[3 * r + 0];
    pay.y = X[3 * r + 1];
    pay.z = X[3 * r + 2];
    pay.w = __int_as_float(r);
    g_pts[dst] = pay;
}

// ---- K4: main — one-wave grid, stride over voxel-half chunks ----
__global__ void __launch_bounds__(256, 6)
voxel_main_kernel(const float* __restrict__ W,
                  float* __restrict__ out)
{
    __shared__ float2 Wp[3][32];     // (sin,cos) weight pairs, angle a=3f+d
    __shared__ float  Wraw[3][4];    // raw x weights
    const int t = threadIdx.x;

    for (int chunk = blockIdx.x; chunk < NCHUNKS; chunk += K4_BLOCKS) {
        const int v    = chunk >> 1;
        const int half = chunk & 1;

        if (chunk != blockIdx.x) __syncthreads();   // protect smem re-stage
        if (t < 90) {
            const int c = t / 30, a = t - 30 * c;
            const int f = a / 3, d = a - 3 * f;
            const float* row = W + (3 * v + c) * 63;
            Wp[c][a] = make_float2(row[3 + 6 * f + d], row[3 + 6 * f + 3 + d]);
        } else if (t < 99) {
            const int u = t - 90;
            const int c = u / 3, d = u - 3 * c;
            Wraw[c][d] = W[(3 * v + c) * 63 + d];
        }
        __syncthreads();

        const int start = g_binstart[v];
        const int cnt   = g_binstart[v + 1] - start;

        for (int i = half * 256 + t; i < cnt; i += 512) {
            const float4 pay = g_pts[start + i];
            const float x0 = pay.x, x1 = pay.y, x2 = pay.z;
            const int   r  = __float_as_int(pay.w);

            float a0 = x0 * Wraw[0][0];
            a0 = fmaf(x1, Wraw[0][1], a0); a0 = fmaf(x2, Wraw[0][2], a0);
            float a1 = x0 * Wraw[1][0];
            a1 = fmaf(x1, Wraw[1][1], a1); a1 = fmaf(x2, Wraw[1][2], a1);
            float a2 = x0 * Wraw[2][0];
            a2 = fmaf(x1, Wraw[2][1], a2); a2 = fmaf(x2, Wraw[2][2], a2);

            // base angles (f=0)
            float s0, c0, s1, c1, s2, c2;
            __sincosf(x0, &s0, &c0);
            __sincosf(x1, &s1, &c1);
            __sincosf(x2, &s2, &c2);

#pragma unroll 2
            for (int f = 0; f < 10; ++f) {
                const int a = 3 * f;
                const float2 w00 = Wp[0][a], w01 = Wp[0][a + 1], w02 = Wp[0][a + 2];
                a0 = fmaf(s0, w00.x, a0); a0 = fmaf(c0, w00.y, a0);
                a0 = fmaf(s1, w01.x, a0); a0 = fmaf(c1, w01.y, a0);
                a0 = fmaf(s2, w02.x, a0); a0 = fmaf(c2, w02.y, a0);
                const float2 w10 = Wp[1][a], w11 = Wp[1][a + 1], w12 = Wp[1][a + 2];
                a1 = fmaf(s0, w10.x, a1); a1 = fmaf(c0, w10.y, a1);
                a1 = fmaf(s1, w11.x, a1); a1 = fmaf(c1, w11.y, a1);
                a1 = fmaf(s2, w12.x, a1); a1 = fmaf(c2, w12.y, a1);
                const float2 w20 = Wp[2][a], w21 = Wp[2][a + 1], w22 = Wp[2][a + 2];
                a2 = fmaf(s0, w20.x, a2); a2 = fmaf(c0, w20.y, a2);
                a2 = fmaf(s1, w21.x, a2); a2 = fmaf(c1, w21.y, a2);
                a2 = fmaf(s2, w22.x, a2); a2 = fmaf(c2, w22.y, a2);

                if (f < 9) {   // double-angle: s'=2sc, c'=c^2-s^2
                    float ts, tc;
                    ts = s0 * c0; tc = fmaf(c0, c0, -(s0 * s0)); s0 = ts + ts; c0 = tc;
                    ts = s1 * c1; tc = fmaf(c1, c1, -(s1 * s1)); s1 = ts + ts; c1 = tc;
                    ts = s2 * c2; tc = fmaf(c2, c2, -(s2 * s2)); s2 = ts + ts; c2 = tc;
                }
            }

            out[3 * r + 0] = a0;
            out[3 * r + 1] = a1;
            out[3 * r + 2] = a2;
        }
    }
}

extern "C" void kernel_launch(void* const* d_in, const int* in_sizes, int n_in,
                              void* d_out, int out_size)
{
    const float* X         = (const float*)d_in[0];
    const float* W         = (const float*)d_in[1];
    const int*   row_ids   = (const int*)d_in[2];
    const int*   voxel_ids = (const int*)d_in[3];
    float*       out       = (float*)d_out;

    const int n = in_sizes[0] / 3;               // N_POINTS
    const int nb = (n + 255) / 256;

    rank_kernel<<<nb, 256>>>(voxel_ids, n);
    scan_kernel<<<1, NUM_VOXELS>>>(n);
    scatter_kernel<<<nb, 256>>>(X, row_ids, voxel_ids, n);
    voxel_main_kernel<<<K4_BLOCKS, 256>>>(W, out);
}

// round 17
// speedup vs baseline: 2.1608x; 1.1102x over previous
#include <cuda_runtime.h>

// out[r][c] = posenc(X[r]) . W[3*voxel_ids[p] + c],  r = row_ids[p]
//
//  K1 rank:    pos[p] = atomicAdd(cnt[v],1)          (measured-best setup, R9)
//  K2 scan:    exclusive scan -> g_binstart; counters self-reset
//  K3 scatter: g_pts[binstart[v]+pos[p]] = float4(x, bits(r))
//  K4 main:    R9 config (grid 1024 = 2 CTAs/voxel, cap (256,6), float2
//              (sin,cos)-paired smem weights, double-angle recurrence) +
//              THIS ROUND: packed fma.rn.f32x2 accumulation — one FFMA2 per
//              (angle, channel) instead of two FFMA (189 -> 90+30 instrs/pt).

#define NUM_VOXELS 512
#define NPTS_MAX (1 << 18)
#define PAD 32                    // counter stride in ints = 128 B

__device__ int    g_cnt[NUM_VOXELS * PAD];   // zero-init; self-reset by K2
__device__ int    g_pos[NPTS_MAX];
__device__ int    g_binstart[NUM_VOXELS + 1];
__device__ float4 g_pts[NPTS_MAX];

__device__ __forceinline__ unsigned long long pk2(float lo, float hi)
{
    unsigned long long r;
    asm("mov.b64 %0, {%1, %2};" : "=l"(r) : "f"(lo), "f"(hi));
    return r;
}
__device__ __forceinline__ void vfma2(unsigned long long& acc,
                                      unsigned long long a,
                                      unsigned long long b)
{
    asm("fma.rn.f32x2 %0, %1, %2, %3;" : "=l"(acc) : "l"(a), "l"(b), "l"(acc));
}
__device__ __forceinline__ float upk_sum(unsigned long long v)
{
    float lo, hi;
    asm("mov.b64 {%0, %1}, %2;" : "=f"(lo), "=f"(hi) : "l"(v));
    return lo + hi;
}

// ---- K1: per-point rank within its voxel ----
__global__ void __launch_bounds__(256)
rank_kernel(const int* __restrict__ voxel_ids, int n)
{
    int p = blockIdx.x * 256 + threadIdx.x;
    if (p >= n) return;
    g_pos[p] = atomicAdd(&g_cnt[voxel_ids[p] * PAD], 1);
}

// ---- K2: scan counts -> binstart; self-reset counters ----
__global__ void __launch_bounds__(NUM_VOXELS)
scan_kernel(int n)
{
    __shared__ int sh[NUM_VOXELS];
    const int t = threadIdx.x;
    const int val = g_cnt[t * PAD];
    g_cnt[t * PAD] = 0;                  // reset for next graph replay
    sh[t] = val;
    __syncthreads();
#pragma unroll
    for (int off = 1; off < NUM_VOXELS; off <<= 1) {
        int x = sh[t];
        if (t >= off) x += sh[t - off];
        __syncthreads();
        sh[t] = x;
        __syncthreads();
    }
    g_binstart[t] = sh[t] - val;         // exclusive
    if (t == NUM_VOXELS - 1) g_binstart[NUM_VOXELS] = n;
}

// ---- K3: scatter payload into voxel-sorted order ----
__global__ void __launch_bounds__(256)
scatter_kernel(const float* __restrict__ X,
               const int* __restrict__ row_ids,
               const int* __restrict__ voxel_ids,
               int n)
{
    int p = blockIdx.x * 256 + threadIdx.x;
    if (p >= n) return;
    const int v = voxel_ids[p];
    const int dst = g_binstart[v] + g_pos[p];
    const int r = row_ids[p];
    float4 pay;
    pay.x = X[3 * r + 0];
    pay.y = X[3 * r + 1];
    pay.z = X[3 * r + 2];
    pay.w = __int_as_float(r);
    g_pts[dst] = pay;
}

// ---- K4: main — 2 CTAs/voxel, f32x2 packed accumulation ----
__global__ void __launch_bounds__(256, 6)
voxel_main_kernel(const float* __restrict__ W,
                  float* __restrict__ out)
{
    __shared__ float2 Wp[3][32];     // (sin,cos) weight pairs, angle a=3f+d
    __shared__ float  Wraw[3][4];    // raw x weights
    const int v    = blockIdx.x >> 1;
    const int half = blockIdx.x & 1;
    const int t = threadIdx.x;

    if (t < 90) {
        const int c = t / 30, a = t - 30 * c;
        const int f = a / 3, d = a - 3 * f;
        const float* row = W + (3 * v + c) * 63;
        Wp[c][a] = make_float2(row[3 + 6 * f + d], row[3 + 6 * f + 3 + d]);
    } else if (t < 99) {
        const int u = t - 90;
        const int c = u / 3, d = u - 3 * c;
        Wraw[c][d] = W[(3 * v + c) * 63 + d];
    }
    __syncthreads();

    const unsigned long long* __restrict__ Wp0 =
        reinterpret_cast<const unsigned long long*>(&Wp[0][0]);
    const unsigned long long* __restrict__ Wp1 =
        reinterpret_cast<const unsigned long long*>(&Wp[1][0]);
    const unsigned long long* __restrict__ Wp2 =
        reinterpret_cast<const unsigned long long*>(&Wp[2][0]);

    const int start = g_binstart[v];
    const int cnt   = g_binstart[v + 1] - start;

    for (int i = half * 256 + t; i < cnt; i += 512) {
        const float4 pay = g_pts[start + i];
        const float x0 = pay.x, x1 = pay.y, x2 = pay.z;
        const int   r  = __float_as_int(pay.w);

        // raw channels (scalar, 9 FMAs), seeded into packed acc lo-halves
        float r0 = x0 * Wraw[0][0];
        r0 = fmaf(x1, Wraw[0][1], r0); r0 = fmaf(x2, Wraw[0][2], r0);
        float r1 = x0 * Wraw[1][0];
        r1 = fmaf(x1, Wraw[1][1], r1); r1 = fmaf(x2, Wraw[1][2], r1);
        float r2 = x0 * Wraw[2][0];
        r2 = fmaf(x1, Wraw[2][1], r2); r2 = fmaf(x2, Wraw[2][2], r2);

        unsigned long long A0 = pk2(r0, 0.0f);
        unsigned long long A1 = pk2(r1, 0.0f);
        unsigned long long A2 = pk2(r2, 0.0f);

        // base angles (f=0)
        float s0, c0, s1, c1, s2, c2;
        __sincosf(x0, &s0, &c0);
        __sincosf(x1, &s1, &c1);
        __sincosf(x2, &s2, &c2);

#pragma unroll 2
        for (int f = 0; f < 10; ++f) {
            const int a = 3 * f;
            const unsigned long long SC0 = pk2(s0, c0);
            const unsigned long long SC1 = pk2(s1, c1);
            const unsigned long long SC2 = pk2(s2, c2);

            vfma2(A0, SC0, Wp0[a]); vfma2(A0, SC1, Wp0[a + 1]); vfma2(A0, SC2, Wp0[a + 2]);
            vfma2(A1, SC0, Wp1[a]); vfma2(A1, SC1, Wp1[a + 1]); vfma2(A1, SC2, Wp1[a + 2]);
            vfma2(A2, SC0, Wp2[a]); vfma2(A2, SC1, Wp2[a + 1]); vfma2(A2, SC2, Wp2[a + 2]);

            if (f < 9) {   // double-angle: s'=2sc, c'=c^2-s^2
                float ts, tc;
                ts = s0 * c0; tc = fmaf(c0, c0, -(s0 * s0)); s0 = ts + ts; c0 = tc;
                ts = s1 * c1; tc = fmaf(c1, c1, -(s1 * s1)); s1 = ts + ts; c1 = tc;
                ts = s2 * c2; tc = fmaf(c2, c2, -(s2 * s2)); s2 = ts + ts; c2 = tc;
            }
        }

        out[3 * r + 0] = upk_sum(A0);
        out[3 * r + 1] = upk_sum(A1);
        out[3 * r + 2] = upk_sum(A2);
    }
}

extern "C" void kernel_launch(void* const* d_in, const int* in_sizes, int n_in,
                              void* d_out, int out_size)
{
    const float* X         = (const float*)d_in[0];
    const float* W         = (const float*)d_in[1];
    const int*   row_ids   = (const int*)d_in[2];
    const int*   voxel_ids = (const int*)d_in[3];
    float*       out       = (float*)d_out;

    const int n = in_sizes[0] / 3;               // N_POINTS
    const int nb = (n + 255) / 256;

    rank_kernel<<<nb, 256>>>(voxel_ids, n);
    scan_kernel<<<1, NUM_VOXELS>>>(n);
    scatter_kernel<<<nb, 256>>>(X, row_ids, voxel_ids, n);
    voxel_main_kernel<<<NUM_VOXELS * 2, 256>>>(W, out);
}